// round 9
// baseline (speedup 1.0000x reference)
#include <cuda_runtime.h>
#include <stdint.h>

// carry_save_adder: exact-binary reduction.
// S_b = sum over kept i of value(x[b,i,:]); out bits = S_b & 0xFFFF, carry = S_b >> 16.
// Non-persistent in-order CTAs, 512 threads = 16 rows (64KB) per CTA.
// Cross-wave L2 prefetch: each thread prefetches one 128B line of the CTA
// one wave (+512 CTAs) ahead, bridging DRAM idle at wave transitions.
// Loads: ld.global.nc with L2::256B fetch granularity. FFMA-imm nibble math.

#define PF_DIST 512   // CTAs ahead (~one resident wave)

__device__ __forceinline__ float4 ldg_nc_256B(const float4* p) {
    float4 v;
    asm("ld.global.nc.L2::256B.v4.f32 {%0,%1,%2,%3}, [%4];"
        : "=f"(v.x), "=f"(v.y), "=f"(v.z), "=f"(v.w)
        : "l"(p));
    return v;
}

__global__ void __launch_bounds__(512)
csa_kernel(const float4* __restrict__ x, const int* __restrict__ mask,
           float* __restrict__ out, int B)
{
    const unsigned FULL = 0xFFFFFFFFu;
    const int lane = threadIdx.x & 31;
    const int warp = (blockIdx.x << 4) + (threadIdx.x >> 5);

    // Cross-wave prefetch: cover the 64KB of CTA (blockIdx + PF_DIST);
    // 512 threads x 128B = 64KB.
    {
        long pfrow0 = ((long)blockIdx.x + PF_DIST) << 4;       // first row of target CTA
        if (pfrow0 < B) {
            const char* p = (const char*)x + (pfrow0 << 12) + ((long)threadIdx.x << 7);
            asm volatile("prefetch.global.L2 [%0];" :: "l"(p));
        }
    }

    if (warp >= B) return;

    // Keep mask over the 64 values (indices 0,1 always kept).
    const unsigned mb_lo = __ballot_sync(FULL, mask[lane]      > 0) | 3u;
    const unsigned mb_hi = __ballot_sync(FULL, mask[lane + 32] > 0);

    // Chunk t of this lane holds value index i = 8t + (lane>>2); keep weight:
    const unsigned q = (unsigned)lane >> 2;
    float keepf[8];
    #pragma unroll
    for (int t = 0; t < 8; ++t) {
        unsigned bit = (t < 4) ? ((mb_lo >> (8 * t + q)) & 1u)
                               : ((mb_hi >> (8 * (t - 4) + q)) & 1u);
        keepf[t] = bit ? 1.0f : 0.0f;
    }
    // Loop-invariant nibble weight 2^((lane&3)*4).
    const float wgt = __int_as_float((127 + (((int)lane & 3) << 2)) << 23);

    const float4* row = x + (size_t)warp * 256;

    float sumf = 0.0f;
    #pragma unroll
    for (int t = 0; t < 8; ++t) {
        float4 v = ldg_nc_256B(&row[lane + (t << 5)]);
        float part = v.x;
        part = fmaf(v.y, 2.0f, part);
        part = fmaf(v.z, 4.0f, part);
        part = fmaf(v.w, 8.0f, part);
        sumf = fmaf(part, keepf[t], sumf);
    }
    sumf *= wgt;

    // Warp reduction (exact: integer-valued floats, total < 2^22).
    #pragma unroll
    for (int off = 16; off; off >>= 1)
        sumf += __shfl_xor_sync(FULL, sumf, off);

    const unsigned s = (unsigned)sumf;
    if (lane < 16)
        out[(size_t)warp * 16 + lane] = (float)((s >> lane) & 1u);
    else if (lane == 16)
        out[(size_t)B * 16 + warp] = (float)(s >> 16);
}

extern "C" void kernel_launch(void* const* d_in, const int* in_sizes, int n_in,
                              void* d_out, int out_size)
{
    const float4* x   = (const float4*)d_in[0];   // (B, 64, 16) float32
    const int*    msk = (const int*)d_in[1];      // (64,) int32
    float*        out = (float*)d_out;            // B*16 output bits, then B carries

    int B = in_sizes[0] / 1024;                   // 64*16 floats per batch row
    int blocks = (B + 15) / 16;                   // 16 rows per 512-thread CTA
    csa_kernel<<<blocks, 512>>>(x, msk, out, B);
}

// round 10
// speedup vs baseline: 1.0920x; 1.0920x over previous
#include <cuda_runtime.h>
#include <stdint.h>

// carry_save_adder: exact-binary reduction.
// S_b = sum over kept i of value(x[b,i,:]); out bits = S_b & 0xFFFF, carry = S_b >> 16.
// Non-persistent in-order CTAs; 1024 threads = 32 rows (128KB) per CTA
// (fewest scheduling events at full occupancy). One warp per row.
// Loads: ld.global.nc + L2::256B fetch granularity + evict_first policy.
// FFMA-imm nibble accumulation, loop-invariant weight 2^((lane&3)*4), exact fp32.

__device__ __forceinline__ float4 ldg_stream(const float4* p, unsigned long long pol) {
    float4 v;
    asm("ld.global.nc.L2::cache_hint.L2::256B.v4.f32 {%0,%1,%2,%3}, [%4], %5;"
        : "=f"(v.x), "=f"(v.y), "=f"(v.z), "=f"(v.w)
        : "l"(p), "l"(pol));
    return v;
}

__global__ void __launch_bounds__(1024)
csa_kernel(const float4* __restrict__ x, const int* __restrict__ mask,
           float* __restrict__ out, int B)
{
    const unsigned FULL = 0xFFFFFFFFu;
    const int lane = threadIdx.x & 31;
    const int warp = (blockIdx.x << 5) + (threadIdx.x >> 5);
    if (warp >= B) return;

    unsigned long long pol;
    asm("createpolicy.fractional.L2::evict_first.b64 %0, 1.0;" : "=l"(pol));

    // Keep mask over the 64 values (indices 0,1 always kept).
    const unsigned mb_lo = __ballot_sync(FULL, mask[lane]      > 0) | 3u;
    const unsigned mb_hi = __ballot_sync(FULL, mask[lane + 32] > 0);

    // Chunk t of this lane holds value index i = 8t + (lane>>2); keep weight:
    const unsigned q = (unsigned)lane >> 2;
    float keepf[8];
    #pragma unroll
    for (int t = 0; t < 8; ++t) {
        unsigned bit = (t < 4) ? ((mb_lo >> (8 * t + q)) & 1u)
                               : ((mb_hi >> (8 * (t - 4) + q)) & 1u);
        keepf[t] = bit ? 1.0f : 0.0f;
    }
    // Loop-invariant nibble weight 2^((lane&3)*4).
    const float wgt = __int_as_float((127 + (((int)lane & 3) << 2)) << 23);

    const float4* row = x + (size_t)warp * 256;

    float sumf = 0.0f;
    #pragma unroll
    for (int t = 0; t < 8; ++t) {
        float4 v = ldg_stream(&row[lane + (t << 5)], pol);
        float part = v.x;
        part = fmaf(v.y, 2.0f, part);
        part = fmaf(v.z, 4.0f, part);
        part = fmaf(v.w, 8.0f, part);
        sumf = fmaf(part, keepf[t], sumf);
    }
    sumf *= wgt;

    // Warp reduction (exact: integer-valued floats, total < 2^22).
    #pragma unroll
    for (int off = 16; off; off >>= 1)
        sumf += __shfl_xor_sync(FULL, sumf, off);

    const unsigned s = (unsigned)sumf;
    if (lane < 16)
        out[(size_t)warp * 16 + lane] = (float)((s >> lane) & 1u);
    else if (lane == 16)
        out[(size_t)B * 16 + warp] = (float)(s >> 16);
}

extern "C" void kernel_launch(void* const* d_in, const int* in_sizes, int n_in,
                              void* d_out, int out_size)
{
    const float4* x   = (const float4*)d_in[0];   // (B, 64, 16) float32
    const int*    msk = (const int*)d_in[1];      // (64,) int32
    float*        out = (float*)d_out;            // B*16 output bits, then B carries

    int B = in_sizes[0] / 1024;                   // 64*16 floats per batch row
    int blocks = (B + 31) / 32;                   // 32 rows per 1024-thread CTA
    csa_kernel<<<blocks, 1024>>>(x, msk, out, B);
}